// round 13
// baseline (speedup 1.0000x reference)
#include <cuda_runtime.h>
#include <cuda_bf16.h>
#include <cuda_fp16.h>
#include <cstdint>

// ===================== constants =====================
#define NTOK   16384
#define DIM    512
#define INV_T  14.285714285714286f   // 1/0.07
#define MARGIN 0.1f

#define GRIDX   2048                 // CTAs; each: fixed 64-wide col-tile, 16 row-tiles
#define NROWT   16                   // row-tiles per CTA
#define B_CHUNK 8192                 // 64 rows x 128B
#define B_BYTES (8 * B_CHUNK)        // resident B: 64KB
#define A_STAGE 16384                // one A stage (128 rows x 128B)
#define SMEM_SZ (B_BYTES + 3 * A_STAGE + 1024)   // 113KB -> 2 CTAs/SM (226.5 <= 228KB)

typedef unsigned long long u64;

// ===================== device globals (no cudaMalloc allowed) =====================
__device__ __nv_bfloat16 g_sn[(size_t)NTOK * DIM];   // fp16 stored via 2-byte array
__device__ __nv_bfloat16 g_tn[(size_t)NTOK * DIM];
__device__ float g_diag[NTOK];
__device__ double g_sum;

// ===================== helpers =====================
__device__ __forceinline__ uint32_t smem_u32(const void* p) {
    uint32_t a;
    asm("{ .reg .u64 t; cvta.to.shared.u64 t, %1; cvt.u32.u64 %0, t; }" : "=r"(a) : "l"(p));
    return a;
}
__device__ __forceinline__ void cp_async16(uint32_t smem, const void* gmem) {
    asm volatile("cp.async.cg.shared.global [%0], [%1], 16;" :: "r"(smem), "l"(gmem));
}
#define CP_COMMIT() asm volatile("cp.async.commit_group;" ::: "memory")
#define CP_WAIT(n)  asm volatile("cp.async.wait_group %0;" :: "n"(n) : "memory")

__device__ __forceinline__ void ldsm4(uint32_t* r, uint32_t addr) {
    asm volatile("ldmatrix.sync.aligned.m8n8.x4.shared.b16 {%0,%1,%2,%3}, [%4];"
                 : "=r"(r[0]), "=r"(r[1]), "=r"(r[2]), "=r"(r[3]) : "r"(addr));
}
// fp16 in / fp16 accum (R11/R12-validated): D = 2 regs
__device__ __forceinline__ void mma16816h(uint32_t* c, const uint32_t* a, uint32_t b0, uint32_t b1) {
    asm volatile(
        "mma.sync.aligned.m16n8k16.row.col.f16.f16.f16.f16 "
        "{%0,%1}, {%2,%3,%4,%5}, {%6,%7}, {%0,%1};"
        : "+r"(c[0]), "+r"(c[1])
        : "r"(a[0]), "r"(a[1]), "r"(a[2]), "r"(a[3]), "r"(b0), "r"(b1));
}
#define SWZ(off) ((off) ^ (((off) >> 3) & 0x70))

// ===================== packed f32x2 helpers =====================
__device__ __forceinline__ u64 pfma(u64 a, u64 b, u64 c) {
    u64 d; asm("fma.rn.f32x2 %0, %1, %2, %3;" : "=l"(d) : "l"(a), "l"(b), "l"(c)); return d;
}
__device__ __forceinline__ u64 pmul(u64 a, u64 b) {
    u64 d; asm("mul.rn.f32x2 %0, %1, %2;" : "=l"(d) : "l"(a), "l"(b)); return d;
}
__device__ __forceinline__ u64 padd(u64 a, u64 b) {
    u64 d; asm("add.rn.f32x2 %0, %1, %2;" : "=l"(d) : "l"(a), "l"(b)); return d;
}
__device__ __forceinline__ u64 pack2(float lo, float hi) {
    u64 d; asm("mov.b64 %0, {%1, %2};" : "=l"(d) : "f"(lo), "f"(hi)); return d;
}
__device__ __forceinline__ void unpack2(uint32_t& lo, uint32_t& hi, u64 x) {
    asm("mov.b64 {%0, %1}, %2;" : "=r"(lo), "=r"(hi) : "l"(x));
}
__device__ __forceinline__ u64 bcast(float v) {
    uint32_t b = __float_as_uint(v);
    return ((u64)b << 32) | b;
}

// ===================== scalar softplus (accurate; finalize only) =====================
__device__ __forceinline__ float softplus_fast(float x) {
    float ax = fminf(fabsf(x), 20.0f);
    float r  = fmaxf(x, 0.0f);
    float t  = ax * -1.4426950408889634f;
    float kf = t + 12582912.0f;
    int   sc = __float_as_int(kf) << 23;
    float f  = t - (kf - 12582912.0f);
    float p  = 1.3333558146e-3f;
    p = fmaf(p, f, 9.6181291918e-3f);
    p = fmaf(p, f, 5.5504108664e-2f);
    p = fmaf(p, f, 2.4022650696e-1f);
    p = fmaf(p, f, 6.9314718056e-1f);
    p = fmaf(p, f, 1.0f);
    float e = __int_as_float(__float_as_int(p) + sc);
    float d = e + 2.0f;
    float y = fmaf(d, -0.16666667f, 0.83333333f);
    y = y * fmaf(-d, y, 2.0f);
    y = y * fmaf(-d, y, 2.0f);
    float z  = e * y;
    float z2 = z * z;
    float q  = 0.22222222f;
    q = fmaf(q, z2, 0.28571429f);
    q = fmaf(q, z2, 0.4f);
    q = fmaf(q, z2, 0.66666667f);
    q = fmaf(q, z2, 2.0f);
    return fmaf(z, q, r);
}

// ===================== kernel 1: L2-normalize 2 rows/block + diag dot, fp32 -> fp16 ======
// 256 threads = 2 rows x 128 threads; float4 loads (16B/thread).
__global__ __launch_bounds__(256) void normalize_kernel(const float* __restrict__ S,
                                                        const float* __restrict__ T) {
    int half = threadIdx.x >> 7;           // 0 or 1: which row of this block
    int t    = threadIdx.x & 127;
    int row  = (blockIdx.x << 1) + half;
    if (blockIdx.x == 0 && threadIdx.x == 0) g_sum = 0.0;

    const float4* s4 = (const float4*)(S + (size_t)row * DIM);
    const float4* t4 = (const float4*)(T + (size_t)row * DIM);
    float4 sv = s4[t];
    float4 tv = t4[t];
    float a = fmaf(sv.x, sv.x, fmaf(sv.y, sv.y, fmaf(sv.z, sv.z, sv.w * sv.w)));
    float b = fmaf(tv.x, tv.x, fmaf(tv.y, tv.y, fmaf(tv.z, tv.z, tv.w * tv.w)));
    float c = fmaf(sv.x, tv.x, fmaf(sv.y, tv.y, fmaf(sv.z, tv.z, sv.w * tv.w)));
    #pragma unroll
    for (int o = 16; o; o >>= 1) {
        a += __shfl_xor_sync(0xffffffffu, a, o);
        b += __shfl_xor_sync(0xffffffffu, b, o);
        c += __shfl_xor_sync(0xffffffffu, c, o);
    }
    __shared__ float sa[2][4], sb[2][4], sc[2][4];
    int w = (threadIdx.x >> 5) & 3;
    if ((threadIdx.x & 31) == 0) { sa[half][w] = a; sb[half][w] = b; sc[half][w] = c; }
    __syncthreads();
    float ta = sa[half][0] + sa[half][1] + sa[half][2] + sa[half][3];
    float tb = sb[half][0] + sb[half][1] + sb[half][2] + sb[half][3];
    float tc = sc[half][0] + sc[half][1] + sc[half][2] + sc[half][3];
    float ia = rsqrtf(ta);
    float ib = rsqrtf(tb);
    if (t == 0) g_diag[row] = tc * ia * ib;
    __half2* so = (__half2*)g_sn + (size_t)row * (DIM / 2) + (t << 1);
    __half2* to = (__half2*)g_tn + (size_t)row * (DIM / 2) + (t << 1);
    so[0] = __float22half2_rn(make_float2(sv.x * ia, sv.y * ia));
    so[1] = __float22half2_rn(make_float2(sv.z * ia, sv.w * ia));
    to[0] = __float22half2_rn(make_float2(tv.x * ib, tv.y * ib));
    to[1] = __float22half2_rn(make_float2(tv.z * ib, tv.w * ib));
}

// ===================== packed softplus pair, accumulated into eL/eS =====================
#define EPI_PAIR(F0, F1) do { \
    u64 _pa = pack2(F0, F1); \
    u64 _x  = pfma(_pa, c_invT, c_negM); \
    u64 _ax = _x & 0x7FFFFFFF7FFFFFFFull; \
    u64 _t  = pmul(_ax, c_negL2E); \
    u64 _kf = padd(_t, c_magic); \
    u64 _f  = pfma(padd(_kf, c_nmagic), c_neg1, _t); \
    u64 _p  = pfma(c_e4, _f, c_e3); \
    _p = pfma(_p, _f, c_e2); \
    _p = pfma(_p, _f, c_e1); \
    _p = pfma(_p, _f, c_one); \
    uint32_t _klo, _khi, _plo, _phi; \
    unpack2(_klo, _khi, _kf); \
    unpack2(_plo, _phi, _p); \
    _plo += _klo << 23; \
    _phi += _khi << 23; \
    u64 _e; asm("mov.b64 %0, {%1, %2};" : "=l"(_e) : "r"(_plo), "r"(_phi)); \
    u64 _nd = pfma(_e, c_neg1, c_neg2); \
    u64 _y  = pfma(_nd, c_16, c_56); \
    _y = pmul(_y, pfma(_nd, _y, c_two)); \
    _y = pmul(_y, pfma(_nd, _y, c_two)); \
    u64 _z  = pmul(_e, _y); \
    u64 _z2 = pmul(_z, _z); \
    u64 _q  = pfma(c_q3, _z2, c_q2); \
    _q = pfma(_q, _z2, c_q1); \
    _q = pfma(_q, _z2, c_two); \
    eL = pfma(_z, _q, eL); \
    eS = padd(eS, _x); \
    eS = padd(eS, _ax); \
} while (0)

#define EPI_PAIR_H(R32) do { \
    float2 _fv = __half22float2(*(__half2*)&(R32)); \
    EPI_PAIR(_fv.x, _fv.y); \
} while (0)

// mainloop over one 128x64 tile into ACC (16 f16x2), epilogue of PREV (1 pair / 2 ks).
// 3-stage A ring, ONE barrier per chunk (prefetch target stage (stg+2)%3 was last read
// at chunk c-1; every thread passed this chunk's top barrier only after finishing c-1).
#define DO_TILE(ACC, PREV) do { \
    _Pragma("unroll") \
    for (int _i = 0; _i < 16; ++_i) ACC[_i] = 0u; \
    _Pragma("unroll") \
    for (int c = 0; c < 8; ++c) { \
        CP_WAIT(1); \
        __syncthreads(); \
        uint32_t aBase = sA + (uint32_t)stg * A_STAGE; \
        uint32_t bBase = sB + (uint32_t)c * B_CHUNK; \
        _Pragma("unroll") \
        for (int ks = 0; ks < 4; ++ks) { \
            uint32_t afr[2][4]; \
            _Pragma("unroll") \
            for (int mi = 0; mi < 2; ++mi) { \
                int row = aRow + (mi << 4); \
                uint32_t kb = (uint32_t)(aKsel + (ks << 5)); \
                ldsm4(afr[mi], aBase + (row << 7) + (kb ^ ((row & 7) << 4))); \
            } \
            _Pragma("unroll") \
            for (int nb = 0; nb < 2; ++nb) { \
                uint32_t bfr[4]; \
                int row = bRow + (nb << 4); \
                uint32_t kb = (uint32_t)(bKsel + (ks << 5)); \
                ldsm4(bfr, bBase + (row << 7) + (kb ^ ((row & 7) << 4))); \
                _Pragma("unroll") \
                for (int mi = 0; mi < 2; ++mi) { \
                    mma16816h(&ACC[((mi << 2) + (nb << 1)) << 1],     afr[mi], bfr[0], bfr[1]); \
                    mma16816h(&ACC[((mi << 2) + (nb << 1) + 1) << 1], afr[mi], bfr[2], bfr[3]); \
                } \
            } \
            if ((ks & 1) == 0) EPI_PAIR_H(PREV[(c << 1) + (ks >> 1)]); \
        } \
        { \
            const uint8_t* psrc = (c < 6) ? gAc : gAn; \
            uint32_t pch = (c < 6) ? (uint32_t)(c + 2) : (uint32_t)(c - 6); \
            int _s2 = stg + 2; if (_s2 >= 3) _s2 -= 3; \
            uint32_t pst = sA + (uint32_t)_s2 * A_STAGE; \
            _Pragma("unroll") \
            for (int _i = 0; _i < 4; ++_i) cp_async16(pst + soff[_i], psrc + gofs[_i] + pch * 128u); \
            CP_COMMIT(); \
        } \
        if (++stg == 3) stg = 0; \
    } \
    gAc = gAn; \
    tcount++; \
    { int tn = (tcount + 1 < NROWT) ? (tcount + 1) : tcount; \
      gAn = (const uint8_t*)g_sn + ((size_t)((tn << 3) + rband) << 17); } \
} while (0)

// ===================== kernel 2: 2-CTA/SM fp16 GEMM (128x64 tiles) + pipelined epilogue =====
// 256 threads (8 warps, 4x2), warp tile 32x32. B col-tile (64 cols) resident: 64KB.
__global__ __launch_bounds__(256, 2) void gemm_loss_kernel() {
    extern __shared__ uint8_t dynsmem[];
    __shared__ float s_red[8];

    int tid  = threadIdx.x;
    int wid  = tid >> 5;
    int lane = tid & 31;
    int bid  = blockIdx.x;

    uint32_t rbase = smem_u32(dynsmem);
    uint32_t base  = (rbase + 1023u) & ~1023u;
    uint32_t sB = base;                  // 8 resident B chunks (64 rows each)
    uint32_t sA = base + B_BYTES;        // 3 A stages

    // this CTA: fixed 64-wide col-tile bc (0..255), row-tiles (it<<3)+rband
    int rband = bid & 7;
    int bc    = bid >> 3;
    int tcount = 0;
    const uint8_t* gAc = (const uint8_t*)g_sn + ((size_t)rband << 17);
    const uint8_t* gAn = (const uint8_t*)g_sn + ((size_t)(8 + rband) << 17);
    const uint8_t* gB  = (const uint8_t*)g_tn + ((size_t)bc << 16);   // 64 rows * 1024B

    // A cp.async slots: 16KB chunk / 256 threads = 4 x 16B
    uint32_t soff[4], gofs[4];
    #pragma unroll
    for (int i = 0; i < 4; i++) {
        int idx = tid + (i << 8);
        int r   = idx >> 3, sg = idx & 7;
        soff[i] = SWZ((r << 7) + (sg << 4));
        gofs[i] = r * (DIM * 2) + (sg << 4);
    }
    // B cp.async slots: 8KB chunk / 256 threads = 2 x 16B
    uint32_t soffB[2], gofsB[2];
    #pragma unroll
    for (int i = 0; i < 2; i++) {
        int idx = tid + (i << 8);
        int r   = idx >> 3, sg = idx & 7;
        soffB[i] = SWZ((r << 7) + (sg << 4));
        gofsB[i] = r * (DIM * 2) + (sg << 4);
    }

    // warp grid 4(M) x 2(N); warp tile 32x32
    int wm = wid & 3, wn = wid >> 2;
    int aRow  = (wm << 5) + (lane & 15);
    int aKsel = (lane >> 4) << 4;
    int bRow  = (wn << 5) + (lane & 7) + ((lane & 16) >> 1);
    int bKsel = (lane & 8) << 1;

    // epilogue constants
    const u64 c_invT   = bcast(INV_T);
    const u64 c_negM   = bcast(-MARGIN);
    const u64 c_negL2E = bcast(-1.4426950408889634f);
    const u64 c_magic  = bcast(12582912.0f);
    const u64 c_nmagic = bcast(-12582912.0f);
    const u64 c_neg1   = bcast(-1.0f);
    const u64 c_neg2   = bcast(-2.0f);
    const u64 c_two    = bcast(2.0f);
    const u64 c_e4     = bcast(9.6181291918e-3f);
    const u64 c_e3     = bcast(5.5504108664e-2f);
    const u64 c_e2     = bcast(2.4022650696e-1f);
    const u64 c_e1     = bcast(6.9314718056e-1f);
    const u64 c_one    = bcast(1.0f);
    const u64 c_16     = bcast(0.16666667f);
    const u64 c_56     = bcast(0.83333333f);
    const u64 c_q3     = bcast(0.28571429f);
    const u64 c_q2     = bcast(0.4f);
    const u64 c_q1     = bcast(0.66666667f);

    u64 eL = 0ull, eS = 0ull;
    uint32_t accA[16], accB[16];
    #pragma unroll
    for (int i = 0; i < 16; i++) accB[i] = 0u;
    int stg = 0;                         // A-stage ring counter

    // ---- prologue: resident B (1 group), then A chunks 0,1 into stages 0,1 ----
    #pragma unroll
    for (int c = 0; c < 8; ++c)
        #pragma unroll
        for (int i = 0; i < 2; ++i)
            cp_async16(sB + (uint32_t)c * B_CHUNK + soffB[i], gB + gofsB[i] + c * 128u);
    CP_COMMIT();
    #pragma unroll
    for (int i = 0; i < 4; ++i) cp_async16(sA + soff[i], gAc + gofs[i]);
    CP_COMMIT();
    #pragma unroll
    for (int i = 0; i < 4; ++i) cp_async16(sA + A_STAGE + soff[i], gAc + gofs[i] + 128u);
    CP_COMMIT();

    // ---- 16 tiles, banks alternating; epilogue of previous tile rides in mainloop ----
    #pragma unroll 1
    for (int it = 0; it < NROWT / 2; ++it) {
        DO_TILE(accA, accB);
        if (it == 0) { eL = 0ull; eS = 0ull; }   // discard epi of the zero bank
        DO_TILE(accB, accA);
    }
    CP_WAIT(0);

    // ---- final epilogue: last bank ----
    #pragma unroll
    for (int p = 0; p < 16; ++p) EPI_PAIR_H(accB[p]);

    // ---- reduce: one atomicAdd per CTA ----
    uint32_t slo, shi, llo, lhi;
    unpack2(slo, shi, eS);
    unpack2(llo, lhi, eL);
    float sum = __uint_as_float(llo) + __uint_as_float(lhi);
    sum = fmaf(__uint_as_float(slo) + __uint_as_float(shi), 0.5f, sum);

    #pragma unroll
    for (int o = 16; o; o >>= 1) sum += __shfl_xor_sync(0xffffffffu, sum, o);
    if (lane == 0) s_red[wid] = sum;
    __syncthreads();
    if (tid == 0) {
        float s = 0.f;
        #pragma unroll
        for (int i = 0; i < 8; i++) s += s_red[i];
        atomicAdd(&g_sum, (double)s);
    }
}

// ===================== kernel 3: diagonal correction + finalize =====================
__global__ __launch_bounds__(1024) void finalize_kernel(float* out) {
    __shared__ float s_red[32];
    int tid = threadIdx.x;
    float corr = 0.f;
    for (int i = tid; i < NTOK; i += 1024) {
        float l = g_diag[i] * INV_T;
        corr += softplus_fast(-l - MARGIN) - softplus_fast(l - MARGIN);
    }
    #pragma unroll
    for (int o = 16; o; o >>= 1) corr += __shfl_xor_sync(0xffffffffu, corr, o);
    int w = tid >> 5, l = tid & 31;
    if (l == 0) s_red[w] = corr;
    __syncthreads();
    if (tid == 0) {
        float tc = 0.f;
        #pragma unroll
        for (int i = 0; i < 32; i++) tc += s_red[i];
        out[0] = (float)((g_sum + (double)tc) * (1.0 / (double)NTOK));
    }
}

// ===================== launch =====================
extern "C" void kernel_launch(void* const* d_in, const int* in_sizes, int n_in,
                              void* d_out, int out_size) {
    const float* S = (const float*)d_in[0];
    const float* T = (const float*)d_in[1];
    cudaFuncSetAttribute(gemm_loss_kernel,
                         cudaFuncAttributeMaxDynamicSharedMemorySize, SMEM_SZ);
    normalize_kernel<<<NTOK / 2, 256>>>(S, T);
    gemm_loss_kernel<<<GRIDX, 256, SMEM_SZ>>>();
    finalize_kernel<<<1, 1024>>>((float*)d_out);
}

// round 14
// speedup vs baseline: 1.1964x; 1.1964x over previous
#include <cuda_runtime.h>
#include <cuda_bf16.h>
#include <cuda_fp16.h>
#include <cstdint>

// ===================== constants =====================
#define NTOK   16384
#define DIM    512
#define INV_T  14.285714285714286f   // 1/0.07
#define MARGIN 0.1f

#define GRIDX   2048                 // CTAs; each: fixed 64-wide col-tile, 16 row-tiles
#define NROWT   16                   // row-tiles per CTA
#define B_CHUNK 8192                 // 64 rows x 128B
#define B_BYTES (8 * B_CHUNK)        // resident B: 64KB
#define A_STAGE 16384                // one A stage (128 rows x 128B)
#define SMEM_SZ (B_BYTES + 2 * A_STAGE + 1024)   // 97KB -> 2 CTAs/SM with real headroom

typedef unsigned long long u64;

// ===================== device globals (no cudaMalloc allowed) =====================
__device__ __nv_bfloat16 g_sn[(size_t)NTOK * DIM];   // fp16 stored via 2-byte array
__device__ __nv_bfloat16 g_tn[(size_t)NTOK * DIM];
__device__ float g_diag[NTOK];
__device__ double g_sum;

// ===================== helpers =====================
__device__ __forceinline__ uint32_t smem_u32(const void* p) {
    uint32_t a;
    asm("{ .reg .u64 t; cvta.to.shared.u64 t, %1; cvt.u32.u64 %0, t; }" : "=r"(a) : "l"(p));
    return a;
}
__device__ __forceinline__ void cp_async16(uint32_t smem, const void* gmem) {
    asm volatile("cp.async.cg.shared.global [%0], [%1], 16;" :: "r"(smem), "l"(gmem));
}
#define CP_COMMIT() asm volatile("cp.async.commit_group;" ::: "memory")
#define CP_WAIT(n)  asm volatile("cp.async.wait_group %0;" :: "n"(n) : "memory")

__device__ __forceinline__ void ldsm4(uint32_t* r, uint32_t addr) {
    asm volatile("ldmatrix.sync.aligned.m8n8.x4.shared.b16 {%0,%1,%2,%3}, [%4];"
                 : "=r"(r[0]), "=r"(r[1]), "=r"(r[2]), "=r"(r[3]) : "r"(addr));
}
// fp16 in / fp16 accum (R11/R12-validated): D = 2 regs
__device__ __forceinline__ void mma16816h(uint32_t* c, const uint32_t* a, uint32_t b0, uint32_t b1) {
    asm volatile(
        "mma.sync.aligned.m16n8k16.row.col.f16.f16.f16.f16 "
        "{%0,%1}, {%2,%3,%4,%5}, {%6,%7}, {%0,%1};"
        : "+r"(c[0]), "+r"(c[1])
        : "r"(a[0]), "r"(a[1]), "r"(a[2]), "r"(a[3]), "r"(b0), "r"(b1));
}
#define SWZ(off) ((off) ^ (((off) >> 3) & 0x70))

// ===================== packed f32x2 helpers =====================
__device__ __forceinline__ u64 pfma(u64 a, u64 b, u64 c) {
    u64 d; asm("fma.rn.f32x2 %0, %1, %2, %3;" : "=l"(d) : "l"(a), "l"(b), "l"(c)); return d;
}
__device__ __forceinline__ u64 pmul(u64 a, u64 b) {
    u64 d; asm("mul.rn.f32x2 %0, %1, %2;" : "=l"(d) : "l"(a), "l"(b)); return d;
}
__device__ __forceinline__ u64 padd(u64 a, u64 b) {
    u64 d; asm("add.rn.f32x2 %0, %1, %2;" : "=l"(d) : "l"(a), "l"(b)); return d;
}
__device__ __forceinline__ u64 pack2(float lo, float hi) {
    u64 d; asm("mov.b64 %0, {%1, %2};" : "=l"(d) : "f"(lo), "f"(hi)); return d;
}
__device__ __forceinline__ void unpack2(uint32_t& lo, uint32_t& hi, u64 x) {
    asm("mov.b64 {%0, %1}, %2;" : "=r"(lo), "=r"(hi) : "l"(x));
}
__device__ __forceinline__ u64 bcast(float v) {
    uint32_t b = __float_as_uint(v);
    return ((u64)b << 32) | b;
}

// ===================== scalar softplus (accurate; finalize only) =====================
__device__ __forceinline__ float softplus_fast(float x) {
    float ax = fminf(fabsf(x), 20.0f);
    float r  = fmaxf(x, 0.0f);
    float t  = ax * -1.4426950408889634f;
    float kf = t + 12582912.0f;
    int   sc = __float_as_int(kf) << 23;
    float f  = t - (kf - 12582912.0f);
    float p  = 1.3333558146e-3f;
    p = fmaf(p, f, 9.6181291918e-3f);
    p = fmaf(p, f, 5.5504108664e-2f);
    p = fmaf(p, f, 2.4022650696e-1f);
    p = fmaf(p, f, 6.9314718056e-1f);
    p = fmaf(p, f, 1.0f);
    float e = __int_as_float(__float_as_int(p) + sc);
    float d = e + 2.0f;
    float y = fmaf(d, -0.16666667f, 0.83333333f);
    y = y * fmaf(-d, y, 2.0f);
    y = y * fmaf(-d, y, 2.0f);
    float z  = e * y;
    float z2 = z * z;
    float q  = 0.22222222f;
    q = fmaf(q, z2, 0.28571429f);
    q = fmaf(q, z2, 0.4f);
    q = fmaf(q, z2, 0.66666667f);
    q = fmaf(q, z2, 2.0f);
    return fmaf(z, q, r);
}

// ===================== kernel 1: L2-normalize 2 rows/block + diag dot, fp32 -> fp16 ======
// (R13-validated: 17.2us) 256 threads = 2 rows x 128; float4 loads.
__global__ __launch_bounds__(256) void normalize_kernel(const float* __restrict__ S,
                                                        const float* __restrict__ T) {
    int half = threadIdx.x >> 7;
    int t    = threadIdx.x & 127;
    int row  = (blockIdx.x << 1) + half;
    if (blockIdx.x == 0 && threadIdx.x == 0) g_sum = 0.0;

    const float4* s4 = (const float4*)(S + (size_t)row * DIM);
    const float4* t4 = (const float4*)(T + (size_t)row * DIM);
    float4 sv = s4[t];
    float4 tv = t4[t];
    float a = fmaf(sv.x, sv.x, fmaf(sv.y, sv.y, fmaf(sv.z, sv.z, sv.w * sv.w)));
    float b = fmaf(tv.x, tv.x, fmaf(tv.y, tv.y, fmaf(tv.z, tv.z, tv.w * tv.w)));
    float c = fmaf(sv.x, tv.x, fmaf(sv.y, tv.y, fmaf(sv.z, tv.z, sv.w * tv.w)));
    #pragma unroll
    for (int o = 16; o; o >>= 1) {
        a += __shfl_xor_sync(0xffffffffu, a, o);
        b += __shfl_xor_sync(0xffffffffu, b, o);
        c += __shfl_xor_sync(0xffffffffu, c, o);
    }
    __shared__ float sa[2][4], sb[2][4], sc[2][4];
    int w = (threadIdx.x >> 5) & 3;
    if ((threadIdx.x & 31) == 0) { sa[half][w] = a; sb[half][w] = b; sc[half][w] = c; }
    __syncthreads();
    float ta = sa[half][0] + sa[half][1] + sa[half][2] + sa[half][3];
    float tb = sb[half][0] + sb[half][1] + sb[half][2] + sb[half][3];
    float tc = sc[half][0] + sc[half][1] + sc[half][2] + sc[half][3];
    float ia = rsqrtf(ta);
    float ib = rsqrtf(tb);
    if (t == 0) g_diag[row] = tc * ia * ib;
    __half2* so = (__half2*)g_sn + (size_t)row * (DIM / 2) + (t << 1);
    __half2* to = (__half2*)g_tn + (size_t)row * (DIM / 2) + (t << 1);
    so[0] = __float22half2_rn(make_float2(sv.x * ia, sv.y * ia));
    so[1] = __float22half2_rn(make_float2(sv.z * ia, sv.w * ia));
    to[0] = __float22half2_rn(make_float2(tv.x * ib, tv.y * ib));
    to[1] = __float22half2_rn(make_float2(tv.z * ib, tv.w * ib));
}

// ===================== packed softplus pair, accumulated into eL/eS =====================
#define EPI_PAIR(F0, F1) do { \
    u64 _pa = pack2(F0, F1); \
    u64 _x  = pfma(_pa, c_invT, c_negM); \
    u64 _ax = _x & 0x7FFFFFFF7FFFFFFFull; \
    u64 _t  = pmul(_ax, c_negL2E); \
    u64 _kf = padd(_t, c_magic); \
    u64 _f  = pfma(padd(_kf, c_nmagic), c_neg1, _t); \
    u64 _p  = pfma(c_e4, _f, c_e3); \
    _p = pfma(_p, _f, c_e2); \
    _p = pfma(_p, _f, c_e1); \
    _p = pfma(_p, _f, c_one); \
    uint32_t _klo, _khi, _plo, _phi; \
    unpack2(_klo, _khi, _kf); \
    unpack2(_plo, _phi, _p); \
    _plo += _klo << 23; \
    _phi += _khi << 23; \
    u64 _e; asm("mov.b64 %0, {%1, %2};" : "=l"(_e) : "r"(_plo), "r"(_phi)); \
    u64 _nd = pfma(_e, c_neg1, c_neg2); \
    u64 _y  = pfma(_nd, c_16, c_56); \
    _y = pmul(_y, pfma(_nd, _y, c_two)); \
    _y = pmul(_y, pfma(_nd, _y, c_two)); \
    u64 _z  = pmul(_e, _y); \
    u64 _z2 = pmul(_z, _z); \
    u64 _q  = pfma(c_q3, _z2, c_q2); \
    _q = pfma(_q, _z2, c_q1); \
    _q = pfma(_q, _z2, c_two); \
    eL = pfma(_z, _q, eL); \
    eS = padd(eS, _x); \
    eS = padd(eS, _ax); \
} while (0)

#define EPI_PAIR_H(R32) do { \
    float2 _fv = __half22float2(*(__half2*)&(R32)); \
    EPI_PAIR(_fv.x, _fv.y); \
} while (0)

// mainloop over one 128x64 tile into ACC (16 f16x2), epilogue of PREV (1 pair / 2 ks).
// R12-validated: 2-stage A ring, two barriers per chunk.
#define DO_TILE(ACC, PREV) do { \
    _Pragma("unroll") \
    for (int _i = 0; _i < 16; ++_i) ACC[_i] = 0u; \
    _Pragma("unroll") \
    for (int c = 0; c < 8; ++c) { \
        CP_WAIT(1); \
        __syncthreads(); \
        uint32_t aBase = sA + (uint32_t)(c & 1) * A_STAGE; \
        uint32_t bBase = sB + (uint32_t)c * B_CHUNK; \
        _Pragma("unroll") \
        for (int ks = 0; ks < 4; ++ks) { \
            uint32_t afr[2][4]; \
            _Pragma("unroll") \
            for (int mi = 0; mi < 2; ++mi) { \
                int row = aRow + (mi << 4); \
                uint32_t kb = (uint32_t)(aKsel + (ks << 5)); \
                ldsm4(afr[mi], aBase + (row << 7) + (kb ^ ((row & 7) << 4))); \
            } \
            _Pragma("unroll") \
            for (int nb = 0; nb < 2; ++nb) { \
                uint32_t bfr[4]; \
                int row = bRow + (nb << 4); \
                uint32_t kb = (uint32_t)(bKsel + (ks << 5)); \
                ldsm4(bfr, bBase + (row << 7) + (kb ^ ((row & 7) << 4))); \
                _Pragma("unroll") \
                for (int mi = 0; mi < 2; ++mi) { \
                    mma16816h(&ACC[((mi << 2) + (nb << 1)) << 1],     afr[mi], bfr[0], bfr[1]); \
                    mma16816h(&ACC[((mi << 2) + (nb << 1) + 1) << 1], afr[mi], bfr[2], bfr[3]); \
                } \
            } \
            if ((ks & 1) == 0) EPI_PAIR_H(PREV[(c << 1) + (ks >> 1)]); \
        } \
        __syncthreads(); \
        { \
            const uint8_t* psrc = (c < 6) ? gAc : gAn; \
            uint32_t pch = (c < 6) ? (uint32_t)(c + 2) : (uint32_t)(c - 6); \
            uint32_t pst = sA + (uint32_t)(c & 1) * A_STAGE; \
            _Pragma("unroll") \
            for (int _i = 0; _i < 4; ++_i) cp_async16(pst + soff[_i], psrc + gofs[_i] + pch * 128u); \
            CP_COMMIT(); \
        } \
    } \
    gAc = gAn; \
    tcount++; \
    { int tn = (tcount + 1 < NROWT) ? (tcount + 1) : tcount; \
      gAn = (const uint8_t*)g_sn + ((size_t)((tn << 3) + rband) << 17); } \
} while (0)

// ===================== kernel 2: 2-CTA/SM fp16 GEMM (128x64 tiles) + pipelined epilogue =====
// (R12-validated config) 256 threads (8 warps, 4x2), warp tile 32x32. B resident: 64KB.
__global__ __launch_bounds__(256, 2) void gemm_loss_kernel() {
    extern __shared__ uint8_t dynsmem[];
    __shared__ float s_red[8];

    int tid  = threadIdx.x;
    int wid  = tid >> 5;
    int lane = tid & 31;
    int bid  = blockIdx.x;

    uint32_t rbase = smem_u32(dynsmem);
    uint32_t base  = (rbase + 1023u) & ~1023u;
    uint32_t sB = base;                  // 8 resident B chunks (64 rows each)
    uint32_t sA = base + B_BYTES;        // 2 A stages

    int rband = bid & 7;
    int bc    = bid >> 3;
    int tcount = 0;
    const uint8_t* gAc = (const uint8_t*)g_sn + ((size_t)rband << 17);
    const uint8_t* gAn = (const uint8_t*)g_sn + ((size_t)(8 + rband) << 17);
    const uint8_t* gB  = (const uint8_t*)g_tn + ((size_t)bc << 16);

    // A cp.async slots: 16KB chunk / 256 threads = 4 x 16B
    uint32_t soff[4], gofs[4];
    #pragma unroll
    for (int i = 0; i < 4; i++) {
        int idx = tid + (i << 8);
        int r   = idx >> 3, sg = idx & 7;
        soff[i] = SWZ((r << 7) + (sg << 4));
        gofs[i] = r * (DIM * 2) + (sg << 4);
    }
    // B cp.async slots: 8KB chunk / 256 threads = 2 x 16B
    uint32_t soffB[2], gofsB[2];
    #pragma unroll
    for (int i = 0; i < 2; i++) {
        int idx = tid + (i << 8);
        int r   = idx >> 3, sg = idx & 7;
        soffB[i] = SWZ((r << 7) + (sg << 4));
        gofsB[i] = r * (DIM * 2) + (sg << 4);
    }

    // warp grid 4(M) x 2(N); warp tile 32x32
    int wm = wid & 3, wn = wid >> 2;
    int aRow  = (wm << 5) + (lane & 15);
    int aKsel = (lane >> 4) << 4;
    int bRow  = (wn << 5) + (lane & 7) + ((lane & 16) >> 1);
    int bKsel = (lane & 8) << 1;

    // epilogue constants
    const u64 c_invT   = bcast(INV_T);
    const u64 c_negM   = bcast(-MARGIN);
    const u64 c_negL2E = bcast(-1.4426950408889634f);
    const u64 c_magic  = bcast(12582912.0f);
    const u64 c_nmagic = bcast(-12582912.0f);
    const u64 c_neg1   = bcast(-1.0f);
    const u64 c_neg2   = bcast(-2.0f);
    const u64 c_two    = bcast(2.0f);
    const u64 c_e4     = bcast(9.6181291918e-3f);
    const u64 c_e3     = bcast(5.5504108664e-2f);
    const u64 c_e2     = bcast(2.4022650696e-1f);
    const u64 c_e1     = bcast(6.9314718056e-1f);
    const u64 c_one    = bcast(1.0f);
    const u64 c_16     = bcast(0.16666667f);
    const u64 c_56     = bcast(0.83333333f);
    const u64 c_q3     = bcast(0.28571429f);
    const u64 c_q2     = bcast(0.4f);
    const u64 c_q1     = bcast(0.66666667f);

    u64 eL = 0ull, eS = 0ull;
    uint32_t accA[16], accB[16];
    #pragma unroll
    for (int i = 0; i < 16; i++) accB[i] = 0u;

    // ---- prologue: resident B (1 group), then A chunks 0,1 of first tile ----
    #pragma unroll
    for (int c = 0; c < 8; ++c)
        #pragma unroll
        for (int i = 0; i < 2; ++i)
            cp_async16(sB + (uint32_t)c * B_CHUNK + soffB[i], gB + gofsB[i] + c * 128u);
    CP_COMMIT();
    #pragma unroll
    for (int i = 0; i < 4; ++i) cp_async16(sA + soff[i], gAc + gofs[i]);
    CP_COMMIT();
    #pragma unroll
    for (int i = 0; i < 4; ++i) cp_async16(sA + A_STAGE + soff[i], gAc + gofs[i] + 128u);
    CP_COMMIT();

    // ---- 16 tiles, banks alternating; epilogue of previous tile rides in mainloop ----
    #pragma unroll 1
    for (int it = 0; it < NROWT / 2; ++it) {
        DO_TILE(accA, accB);
        if (it == 0) { eL = 0ull; eS = 0ull; }   // discard epi of the zero bank
        DO_TILE(accB, accA);
    }
    CP_WAIT(0);

    // ---- final epilogue: last bank ----
    #pragma unroll
    for (int p = 0; p < 16; ++p) EPI_PAIR_H(accB[p]);

    // ---- reduce: one atomicAdd per CTA ----
    uint32_t slo, shi, llo, lhi;
    unpack2(slo, shi, eS);
    unpack2(llo, lhi, eL);
    float sum = __uint_as_float(llo) + __uint_as_float(lhi);
    sum = fmaf(__uint_as_float(slo) + __uint_as_float(shi), 0.5f, sum);

    #pragma unroll
    for (int o = 16; o; o >>= 1) sum += __shfl_xor_sync(0xffffffffu, sum, o);
    if (lane == 0) s_red[wid] = sum;
    __syncthreads();
    if (tid == 0) {
        float s = 0.f;
        #pragma unroll
        for (int i = 0; i < 8; i++) s += s_red[i];
        atomicAdd(&g_sum, (double)s);
    }
}

// ===================== kernel 3: diagonal correction + finalize =====================
__global__ __launch_bounds__(1024) void finalize_kernel(float* out) {
    __shared__ float s_red[32];
    int tid = threadIdx.x;
    float corr = 0.f;
    for (int i = tid; i < NTOK; i += 1024) {
        float l = g_diag[i] * INV_T;
        corr += softplus_fast(-l - MARGIN) - softplus_fast(l - MARGIN);
    }
    #pragma unroll
    for (int o = 16; o; o >>= 1) corr += __shfl_xor_sync(0xffffffffu, corr, o);
    int w = tid >> 5, l = tid & 31;
    if (l == 0) s_red[w] = corr;
    __syncthreads();
    if (tid == 0) {
        float tc = 0.f;
        #pragma unroll
        for (int i = 0; i < 32; i++) tc += s_red[i];
        out[0] = (float)((g_sum + (double)tc) * (1.0 / (double)NTOK));
    }
}

// ===================== launch =====================
extern "C" void kernel_launch(void* const* d_in, const int* in_sizes, int n_in,
                              void* d_out, int out_size) {
    const float* S = (const float*)d_in[0];
    const float* T = (const float*)d_in[1];
    cudaFuncSetAttribute(gemm_loss_kernel,
                         cudaFuncAttributeMaxDynamicSharedMemorySize, SMEM_SZ);
    normalize_kernel<<<NTOK / 2, 256>>>(S, T);
    gemm_loss_kernel<<<GRIDX, 256, SMEM_SZ>>>();
    finalize_kernel<<<1, 1024>>>((float*)d_out);
}

// round 17
// speedup vs baseline: 1.2005x; 1.0035x over previous
#include <cuda_runtime.h>
#include <cuda_bf16.h>
#include <cuda_fp16.h>
#include <cstdint>

// ===================== constants =====================
#define NTOK   16384
#define DIM    512
#define INV_T  14.285714285714286f   // 1/0.07
#define MARGIN 0.1f

#define GRIDX   2048                 // CTAs; each: fixed 64-wide col-tile, 16 row-tiles
#define NROWT   16                   // row-tiles per CTA
#define B_CHUNK 8192                 // 64 rows x 128B
#define B_BYTES (8 * B_CHUNK)        // resident B: 64KB
#define A_STAGE 16384                // one A stage (128 rows x 128B)
#define SMEM_SZ (B_BYTES + 2 * A_STAGE + 1024)   // 97KB -> 2 CTAs/SM with real headroom

typedef unsigned long long u64;

// ===================== device globals (no cudaMalloc allowed) =====================
__device__ __nv_bfloat16 g_sn[(size_t)NTOK * DIM];   // fp16 stored via 2-byte array
__device__ __nv_bfloat16 g_tn[(size_t)NTOK * DIM];
__device__ float g_diag[NTOK];
__device__ double g_sum;

// ===================== helpers =====================
__device__ __forceinline__ uint32_t smem_u32(const void* p) {
    uint32_t a;
    asm("{ .reg .u64 t; cvta.to.shared.u64 t, %1; cvt.u32.u64 %0, t; }" : "=r"(a) : "l"(p));
    return a;
}
__device__ __forceinline__ void cp_async16(uint32_t smem, const void* gmem) {
    asm volatile("cp.async.cg.shared.global [%0], [%1], 16;" :: "r"(smem), "l"(gmem));
}
#define CP_COMMIT() asm volatile("cp.async.commit_group;" ::: "memory")
#define CP_WAIT(n)  asm volatile("cp.async.wait_group %0;" :: "n"(n) : "memory")

__device__ __forceinline__ void ldsm4(uint32_t* r, uint32_t addr) {
    asm volatile("ldmatrix.sync.aligned.m8n8.x4.shared.b16 {%0,%1,%2,%3}, [%4];"
                 : "=r"(r[0]), "=r"(r[1]), "=r"(r[2]), "=r"(r[3]) : "r"(addr));
}
// fp16 in / fp16 accum (R11/R12-validated): D = 2 regs
__device__ __forceinline__ void mma16816h(uint32_t* c, const uint32_t* a, uint32_t b0, uint32_t b1) {
    asm volatile(
        "mma.sync.aligned.m16n8k16.row.col.f16.f16.f16.f16 "
        "{%0,%1}, {%2,%3,%4,%5}, {%6,%7}, {%0,%1};"
        : "+r"(c[0]), "+r"(c[1])
        : "r"(a[0]), "r"(a[1]), "r"(a[2]), "r"(a[3]), "r"(b0), "r"(b1));
}
#define SWZ(off) ((off) ^ (((off) >> 3) & 0x70))

// ===================== packed f32x2 helpers =====================
__device__ __forceinline__ u64 pfma(u64 a, u64 b, u64 c) {
    u64 d; asm("fma.rn.f32x2 %0, %1, %2, %3;" : "=l"(d) : "l"(a), "l"(b), "l"(c)); return d;
}
__device__ __forceinline__ u64 pmul(u64 a, u64 b) {
    u64 d; asm("mul.rn.f32x2 %0, %1, %2;" : "=l"(d) : "l"(a), "l"(b)); return d;
}
__device__ __forceinline__ u64 padd(u64 a, u64 b) {
    u64 d; asm("add.rn.f32x2 %0, %1, %2;" : "=l"(d) : "l"(a), "l"(b)); return d;
}
__device__ __forceinline__ u64 pack2(float lo, float hi) {
    u64 d; asm("mov.b64 %0, {%1, %2};" : "=l"(d) : "f"(lo), "f"(hi)); return d;
}
__device__ __forceinline__ void unpack2(uint32_t& lo, uint32_t& hi, u64 x) {
    asm("mov.b64 {%0, %1}, %2;" : "=r"(lo), "=r"(hi) : "l"(x));
}
__device__ __forceinline__ u64 bcast(float v) {
    uint32_t b = __float_as_uint(v);
    return ((u64)b << 32) | b;
}

// ===================== scalar softplus (accurate; finalize only) =====================
__device__ __forceinline__ float softplus_fast(float x) {
    float ax = fminf(fabsf(x), 20.0f);
    float r  = fmaxf(x, 0.0f);
    float t  = ax * -1.4426950408889634f;
    float kf = t + 12582912.0f;
    int   sc = __float_as_int(kf) << 23;
    float f  = t - (kf - 12582912.0f);
    float p  = 1.3333558146e-3f;
    p = fmaf(p, f, 9.6181291918e-3f);
    p = fmaf(p, f, 5.5504108664e-2f);
    p = fmaf(p, f, 2.4022650696e-1f);
    p = fmaf(p, f, 6.9314718056e-1f);
    p = fmaf(p, f, 1.0f);
    float e = __int_as_float(__float_as_int(p) + sc);
    float d = e + 2.0f;
    float y = fmaf(d, -0.16666667f, 0.83333333f);
    y = y * fmaf(-d, y, 2.0f);
    y = y * fmaf(-d, y, 2.0f);
    float z  = e * y;
    float z2 = z * z;
    float q  = 0.22222222f;
    q = fmaf(q, z2, 0.28571429f);
    q = fmaf(q, z2, 0.4f);
    q = fmaf(q, z2, 0.66666667f);
    q = fmaf(q, z2, 2.0f);
    return fmaf(z, q, r);
}

// ===================== kernel 1: L2-normalize 4 rows/block + diag dot, fp32 -> fp16 ======
// 256 threads = 4 rows x 64 threads; 2x float4 loads per tensor (MLP 4), ONE 16B store each.
__global__ __launch_bounds__(256) void normalize_kernel(const float* __restrict__ S,
                                                        const float* __restrict__ T) {
    int rib = threadIdx.x >> 6;            // row in block 0..3
    int t   = threadIdx.x & 63;            // 0..63
    int row = (blockIdx.x << 2) + rib;
    if (blockIdx.x == 0 && threadIdx.x == 0) g_sum = 0.0;

    const float4* s4 = (const float4*)(S + (size_t)row * DIM);
    const float4* t4 = (const float4*)(T + (size_t)row * DIM);
    float4 s0 = s4[2 * t], s1 = s4[2 * t + 1];
    float4 t0 = t4[2 * t], t1 = t4[2 * t + 1];

    float a = fmaf(s0.x, s0.x, fmaf(s0.y, s0.y, fmaf(s0.z, s0.z, s0.w * s0.w)));
    a = fmaf(s1.x, s1.x, fmaf(s1.y, s1.y, fmaf(s1.z, s1.z, fmaf(s1.w, s1.w, a))));
    float b = fmaf(t0.x, t0.x, fmaf(t0.y, t0.y, fmaf(t0.z, t0.z, t0.w * t0.w)));
    b = fmaf(t1.x, t1.x, fmaf(t1.y, t1.y, fmaf(t1.z, t1.z, fmaf(t1.w, t1.w, b))));
    float c = fmaf(s0.x, t0.x, fmaf(s0.y, t0.y, fmaf(s0.z, t0.z, s0.w * t0.w)));
    c = fmaf(s1.x, t1.x, fmaf(s1.y, t1.y, fmaf(s1.z, t1.z, fmaf(s1.w, t1.w, c))));

    #pragma unroll
    for (int o = 16; o; o >>= 1) {
        a += __shfl_xor_sync(0xffffffffu, a, o);
        b += __shfl_xor_sync(0xffffffffu, b, o);
        c += __shfl_xor_sync(0xffffffffu, c, o);
    }
    __shared__ float sa[4][2], sb[4][2], sc[4][2];
    int w = (threadIdx.x >> 5) & 1;        // which warp within the row's 64 threads
    if ((threadIdx.x & 31) == 0) { sa[rib][w] = a; sb[rib][w] = b; sc[rib][w] = c; }
    __syncthreads();
    float ta = sa[rib][0] + sa[rib][1];
    float tb = sb[rib][0] + sb[rib][1];
    float tc = sc[rib][0] + sc[rib][1];
    float ia = rsqrtf(ta);
    float ib = rsqrtf(tb);
    if (t == 0) g_diag[row] = tc * ia * ib;

    __half2 h0 = __float22half2_rn(make_float2(s0.x * ia, s0.y * ia));
    __half2 h1 = __float22half2_rn(make_float2(s0.z * ia, s0.w * ia));
    __half2 h2 = __float22half2_rn(make_float2(s1.x * ia, s1.y * ia));
    __half2 h3 = __float22half2_rn(make_float2(s1.z * ia, s1.w * ia));
    uint4 sv16 = make_uint4(*(uint32_t*)&h0, *(uint32_t*)&h1, *(uint32_t*)&h2, *(uint32_t*)&h3);
    ((uint4*)((__half*)g_sn + (size_t)row * DIM))[t] = sv16;

    h0 = __float22half2_rn(make_float2(t0.x * ib, t0.y * ib));
    h1 = __float22half2_rn(make_float2(t0.z * ib, t0.w * ib));
    h2 = __float22half2_rn(make_float2(t1.x * ib, t1.y * ib));
    h3 = __float22half2_rn(make_float2(t1.z * ib, t1.w * ib));
    uint4 tv16 = make_uint4(*(uint32_t*)&h0, *(uint32_t*)&h1, *(uint32_t*)&h2, *(uint32_t*)&h3);
    ((uint4*)((__half*)g_tn + (size_t)row * DIM))[t] = tv16;
}

// ===================== packed softplus pair, accumulated into eL/eS =====================
#define EPI_PAIR(F0, F1) do { \
    u64 _pa = pack2(F0, F1); \
    u64 _x  = pfma(_pa, c_invT, c_negM); \
    u64 _ax = _x & 0x7FFFFFFF7FFFFFFFull; \
    u64 _t  = pmul(_ax, c_negL2E); \
    u64 _kf = padd(_t, c_magic); \
    u64 _f  = pfma(padd(_kf, c_nmagic), c_neg1, _t); \
    u64 _p  = pfma(c_e4, _f, c_e3); \
    _p = pfma(_p, _f, c_e2); \
    _p = pfma(_p, _f, c_e1); \
    _p = pfma(_p, _f, c_one); \
    uint32_t _klo, _khi, _plo, _phi; \
    unpack2(_klo, _khi, _kf); \
    unpack2(_plo, _phi, _p); \
    _plo += _klo << 23; \
    _phi += _khi << 23; \
    u64 _e; asm("mov.b64 %0, {%1, %2};" : "=l"(_e) : "r"(_plo), "r"(_phi)); \
    u64 _nd = pfma(_e, c_neg1, c_neg2); \
    u64 _y  = pfma(_nd, c_16, c_56); \
    _y = pmul(_y, pfma(_nd, _y, c_two)); \
    _y = pmul(_y, pfma(_nd, _y, c_two)); \
    u64 _z  = pmul(_e, _y); \
    u64 _z2 = pmul(_z, _z); \
    u64 _q  = pfma(c_q3, _z2, c_q2); \
    _q = pfma(_q, _z2, c_q1); \
    _q = pfma(_q, _z2, c_two); \
    eL = pfma(_z, _q, eL); \
    eS = padd(eS, _x); \
    eS = padd(eS, _ax); \
} while (0)

#define EPI_PAIR_H(R32) do { \
    float2 _fv = __half22float2(*(__half2*)&(R32)); \
    EPI_PAIR(_fv.x, _fv.y); \
} while (0)

// mainloop over one 128x64 tile into ACC (16 f16x2), epilogue of PREV (1 pair / 2 ks).
// R12/R14-validated: 2-stage A ring, two barriers per chunk.
#define DO_TILE(ACC, PREV) do { \
    _Pragma("unroll") \
    for (int _i = 0; _i < 16; ++_i) ACC[_i] = 0u; \
    _Pragma("unroll") \
    for (int c = 0; c < 8; ++c) { \
        CP_WAIT(1); \
        __syncthreads(); \
        uint32_t aBase = sA + (uint32_t)(c & 1) * A_STAGE; \
        uint32_t bBase = sB + (uint32_t)c * B_CHUNK; \
        _Pragma("unroll") \
        for (int ks = 0; ks < 4; ++ks) { \
            uint32_t afr[2][4]; \
            _Pragma("unroll") \
            for (int mi = 0; mi < 2; ++mi) { \
                int row = aRow + (mi << 4); \
                uint32_t kb = (uint32_t)(aKsel + (ks << 5)); \
                ldsm4(afr[mi], aBase + (row << 7) + (kb ^ ((row & 7) << 4))); \
            } \
            _Pragma("unroll") \
            for (int nb = 0; nb < 2; ++nb) { \
                uint32_t bfr[4]; \
                int row = bRow + (nb << 4); \
                uint32_t kb = (uint32_t)(bKsel + (ks << 5)); \
                ldsm4(bfr, bBase + (row << 7) + (kb ^ ((row & 7) << 4))); \
                _Pragma("unroll") \
                for (int mi = 0; mi < 2; ++mi) { \
                    mma16816h(&ACC[((mi << 2) + (nb << 1)) << 1],     afr[mi], bfr[0], bfr[1]); \
                    mma16816h(&ACC[((mi << 2) + (nb << 1) + 1) << 1], afr[mi], bfr[2], bfr[3]); \
                } \
            } \
            if ((ks & 1) == 0) EPI_PAIR_H(PREV[(c << 1) + (ks >> 1)]); \
        } \
        __syncthreads(); \
        { \
            const uint8_t* psrc = (c < 6) ? gAc : gAn; \
            uint32_t pch = (c < 6) ? (uint32_t)(c + 2) : (uint32_t)(c - 6); \
            uint32_t pst = sA + (uint32_t)(c & 1) * A_STAGE; \
            _Pragma("unroll") \
            for (int _i = 0; _i < 4; ++_i) cp_async16(pst + soff[_i], psrc + gofs[_i] + pch * 128u); \
            CP_COMMIT(); \
        } \
    } \
    gAc = gAn; \
    tcount++; \
    { int tn = (tcount + 1 < NROWT) ? (tcount + 1) : tcount; \
      gAn = (const uint8_t*)g_sn + ((size_t)((tn << 3) + rband) << 17); } \
} while (0)

// ===================== kernel 2: 2-CTA/SM fp16 GEMM (128x64 tiles) + pipelined epilogue =====
// (R12/R14-validated config) 256 threads (8 warps, 4x2), warp tile 32x32. B resident: 64KB.
__global__ __launch_bounds__(256, 2) void gemm_loss_kernel() {
    extern __shared__ uint8_t dynsmem[];
    __shared__ float s_red[8];

    int tid  = threadIdx.x;
    int wid  = tid >> 5;
    int lane = tid & 31;
    int bid  = blockIdx.x;

    uint32_t rbase = smem_u32(dynsmem);
    uint32_t base  = (rbase + 1023u) & ~1023u;
    uint32_t sB = base;                  // 8 resident B chunks (64 rows each)
    uint32_t sA = base + B_BYTES;        // 2 A stages

    int rband = bid & 7;
    int bc    = bid >> 3;
    int tcount = 0;
    const uint8_t* gAc = (const uint8_t*)g_sn + ((size_t)rband << 17);
    const uint8_t* gAn = (const uint8_t*)g_sn + ((size_t)(8 + rband) << 17);
    const uint8_t* gB  = (const uint8_t*)g_tn + ((size_t)bc << 16);

    // A cp.async slots: 16KB chunk / 256 threads = 4 x 16B
    uint32_t soff[4], gofs[4];
    #pragma unroll
    for (int i = 0; i < 4; i++) {
        int idx = tid + (i << 8);
        int r   = idx >> 3, sg = idx & 7;
        soff[i] = SWZ((r << 7) + (sg << 4));
        gofs[i] = r * (DIM * 2) + (sg << 4);
    }
    // B cp.async slots: 8KB chunk / 256 threads = 2 x 16B
    uint32_t soffB[2], gofsB[2];
    #pragma unroll
    for (int i = 0; i < 2; i++) {
        int idx = tid + (i << 8);
        int r   = idx >> 3, sg = idx & 7;
        soffB[i] = SWZ((r << 7) + (sg << 4));
        gofsB[i] = r * (DIM * 2) + (sg << 4);
    }

    // warp grid 4(M) x 2(N); warp tile 32x32
    int wm = wid & 3, wn = wid >> 2;
    int aRow  = (wm << 5) + (lane & 15);
    int aKsel = (lane >> 4) << 4;
    int bRow  = (wn << 5) + (lane & 7) + ((lane & 16) >> 1);
    int bKsel = (lane & 8) << 1;

    // epilogue constants
    const u64 c_invT   = bcast(INV_T);
    const u64 c_negM   = bcast(-MARGIN);
    const u64 c_negL2E = bcast(-1.4426950408889634f);
    const u64 c_magic  = bcast(12582912.0f);
    const u64 c_nmagic = bcast(-12582912.0f);
    const u64 c_neg1   = bcast(-1.0f);
    const u64 c_neg2   = bcast(-2.0f);
    const u64 c_two    = bcast(2.0f);
    const u64 c_e4     = bcast(9.6181291918e-3f);
    const u64 c_e3     = bcast(5.5504108664e-2f);
    const u64 c_e2     = bcast(2.4022650696e-1f);
    const u64 c_e1     = bcast(6.9314718056e-1f);
    const u64 c_one    = bcast(1.0f);
    const u64 c_16     = bcast(0.16666667f);
    const u64 c_56     = bcast(0.83333333f);
    const u64 c_q3     = bcast(0.28571429f);
    const u64 c_q2     = bcast(0.4f);
    const u64 c_q1     = bcast(0.66666667f);

    u64 eL = 0ull, eS = 0ull;
    uint32_t accA[16], accB[16];
    #pragma unroll
    for (int i = 0; i < 16; i++) accB[i] = 0u;

    // ---- prologue: resident B (1 group), then A chunks 0,1 of first tile ----
    #pragma unroll
    for (int c = 0; c < 8; ++c)
        #pragma unroll
        for (int i = 0; i < 2; ++i)
            cp_async16(sB + (uint32_t)c * B_CHUNK + soffB[i], gB + gofsB[i] + c * 128u);
    CP_COMMIT();
    #pragma unroll
    for (int i = 0; i < 4; ++i) cp_async16(sA + soff[i], gAc + gofs[i]);
    CP_COMMIT();
    #pragma unroll
    for (int i = 0; i < 4; ++i) cp_async16(sA + A_STAGE + soff[i], gAc + gofs[i] + 128u);
    CP_COMMIT();

    // ---- 16 tiles, banks alternating; epilogue of previous tile rides in mainloop ----
    #pragma unroll 1
    for (int it = 0; it < NROWT / 2; ++it) {
        DO_TILE(accA, accB);
        if (it == 0) { eL = 0ull; eS = 0ull; }   // discard epi of the zero bank
        DO_TILE(accB, accA);
    }
    CP_WAIT(0);

    // ---- final epilogue: last bank ----
    #pragma unroll
    for (int p = 0; p < 16; ++p) EPI_PAIR_H(accB[p]);

    // ---- reduce: one atomicAdd per CTA ----
    uint32_t slo, shi, llo, lhi;
    unpack2(slo, shi, eS);
    unpack2(llo, lhi, eL);
    float sum = __uint_as_float(llo) + __uint_as_float(lhi);
    sum = fmaf(__uint_as_float(slo) + __uint_as_float(shi), 0.5f, sum);

    #pragma unroll
    for (int o = 16; o; o >>= 1) sum += __shfl_xor_sync(0xffffffffu, sum, o);
    if (lane == 0) s_red[wid] = sum;
    __syncthreads();
    if (tid == 0) {
        float s = 0.f;
        #pragma unroll
        for (int i = 0; i < 8; i++) s += s_red[i];
        atomicAdd(&g_sum, (double)s);
    }
}

// ===================== kernel 3: diagonal correction + finalize =====================
__global__ __launch_bounds__(1024) void finalize_kernel(float* out) {
    __shared__ float s_red[32];
    int tid = threadIdx.x;
    float corr = 0.f;
    for (int i = tid; i < NTOK; i += 1024) {
        float l = g_diag[i] * INV_T;
        corr += softplus_fast(-l - MARGIN) - softplus_fast(l - MARGIN);
    }
    #pragma unroll
    for (int o = 16; o; o >>= 1) corr += __shfl_xor_sync(0xffffffffu, corr, o);
    int w = tid >> 5, l = tid & 31;
    if (l == 0) s_red[w] = corr;
    __syncthreads();
    if (tid == 0) {
        float tc = 0.f;
        #pragma unroll
        for (int i = 0; i < 32; i++) tc += s_red[i];
        out[0] = (float)((g_sum + (double)tc) * (1.0 / (double)NTOK));
    }
}

// ===================== launch =====================
extern "C" void kernel_launch(void* const* d_in, const int* in_sizes, int n_in,
                              void* d_out, int out_size) {
    const float* S = (const float*)d_in[0];
    const float* T = (const float*)d_in[1];
    cudaFuncSetAttribute(gemm_loss_kernel,
                         cudaFuncAttributeMaxDynamicSharedMemorySize, SMEM_SZ);
    normalize_kernel<<<NTOK / 4, 256>>>(S, T);
    gemm_loss_kernel<<<GRIDX, 256, SMEM_SZ>>>();
    finalize_kernel<<<1, 1024>>>((float*)d_out);
}